// round 1
// baseline (speedup 1.0000x reference)
#include <cuda_runtime.h>
#include <math.h>

#define B_    1024
#define L_    50
#define D_    64
#define S_    2
#define LDX   65          // padded row stride (odd -> bank-conflict-free strided reads)
#define TPB   256
#define NEGV  (-4294967295.0f)

// ---- shared memory layout (floats) ----
#define OFF_IN   0                       // inputs (post first LN), kept for LBA
#define OFF_X    (OFF_IN + L_*LDX)       // running x
#define OFF_T1   (OFF_X  + L_*LDX)      // temp tile 1
#define OFF_T2   (OFF_T1 + L_*LDX)      // temp tile 2
#define OFF_W    (OFF_T2 + L_*LDX)      // 64x64 weight staging
#define OFF_SC   (OFF_W  + D_*D_)       // 50x50 scores / c1 / c2 / softmax scratch
#define OFF_PM   (OFF_SC + L_*L_)       // padding mask (50)
#define OFF_G1   (OFF_PM + 64)          // ie . gw[0:64] per position
#define OFF_GLO  (OFF_G1 + 64)          // glo vector (64)
#define OFF_GW   (OFF_GLO + 64)         // gated_weight (192) + gglo scalar @192
#define SMEM_F   (OFF_GW + 200)
#define SMEM_BYTES (SMEM_F * 4)

__device__ __forceinline__ float warp_sum(float v) {
#pragma unroll
    for (int o = 16; o; o >>= 1) v += __shfl_xor_sync(0xffffffffu, v, o);
    return v;
}
__device__ __forceinline__ float warp_max(float v) {
#pragma unroll
    for (int o = 16; o; o >>= 1) v = fmaxf(v, __shfl_xor_sync(0xffffffffu, v, o));
    return v;
}
__device__ __forceinline__ float sigmoidf_(float x) {
    return 1.0f / (1.0f + expf(-x));
}

// LayerNorm over D=64 for each of L_ rows (warp per row), in place.
__device__ __forceinline__ void ln_rows(float* p) {
    const int lane = threadIdx.x & 31, wid = threadIdx.x >> 5;
    for (int l = wid; l < L_; l += 8) {
        float v0 = p[l*LDX + lane], v1 = p[l*LDX + lane + 32];
        float mean = warp_sum(v0 + v1) * (1.0f/64.0f);
        float d0 = v0 - mean, d1 = v1 - mean;
        float var = warp_sum(d0*d0 + d1*d1) * (1.0f/64.0f);
        float inv = rsqrtf(var + 1e-8f);
        p[l*LDX + lane]      = d0 * inv;
        p[l*LDX + lane + 32] = d1 * inv;
    }
}

// dst[l, d] = sum_k src[l, k] * W[k, d]   (src: L_ x LDX smem, W: 64x64 smem)
// 4x4 register blocking: 16 threads cover d (x4), 16 groups cover rows (x4).
__device__ __forceinline__ void mm_LW(float* __restrict__ dst,
                                      const float* __restrict__ src,
                                      const float* __restrict__ W) {
    const int tid = threadIdx.x;
    const int d0 = tid & 15;
    const int g  = tid >> 4;
    int rb[4];
#pragma unroll
    for (int r = 0; r < 4; ++r) {
        int l = g + r*16; if (l >= L_) l = L_ - 1;
        rb[r] = l * LDX;
    }
    float a[4][4] = {};
#pragma unroll 8
    for (int k = 0; k < D_; ++k) {
        float w[4], xv[4];
#pragma unroll
        for (int c = 0; c < 4; ++c) w[c] = W[k*64 + d0 + c*16];
#pragma unroll
        for (int r = 0; r < 4; ++r) xv[r] = src[rb[r] + k];
#pragma unroll
        for (int r = 0; r < 4; ++r)
#pragma unroll
            for (int c = 0; c < 4; ++c) a[r][c] = fmaf(xv[r], w[c], a[r][c]);
    }
#pragma unroll
    for (int r = 0; r < 4; ++r) {
        const int l = g + r*16;
        if (l < L_) {
#pragma unroll
            for (int c = 0; c < 4; ++c) dst[l*LDX + d0 + c*16] = a[r][c];
        }
    }
}

// scores[q, k] = (Q[q,:] . K[k,:]) / 8, then tril/keymask NEG fill, then * pm[q]
__device__ __forceinline__ void mm_scores(float* __restrict__ sc,
                                          const float* __restrict__ Q,
                                          const float* __restrict__ Kx,
                                          const float* __restrict__ pm) {
    const int tid = threadIdx.x;
    const int kd = tid & 15;
    const int g  = tid >> 4;
    int qb[4], kb[4];
#pragma unroll
    for (int r = 0; r < 4; ++r) {
        int q = g + r*16; if (q >= L_) q = L_ - 1;
        qb[r] = q * LDX;
    }
#pragma unroll
    for (int c = 0; c < 4; ++c) {
        int kk = kd + c*16; if (kk >= L_) kk = L_ - 1;
        kb[c] = kk * LDX;
    }
    float a[4][4] = {};
#pragma unroll 8
    for (int d = 0; d < D_; ++d) {
        float qv[4], kv[4];
#pragma unroll
        for (int r = 0; r < 4; ++r) qv[r] = Q[qb[r] + d];
#pragma unroll
        for (int c = 0; c < 4; ++c) kv[c] = Kx[kb[c] + d];
#pragma unroll
        for (int r = 0; r < 4; ++r)
#pragma unroll
            for (int c = 0; c < 4; ++c) a[r][c] = fmaf(qv[r], kv[c], a[r][c]);
    }
#pragma unroll
    for (int r = 0; r < 4; ++r) {
        const int q = g + r*16;
        if (q >= L_) continue;
        const float pq = pm[q];
#pragma unroll
        for (int c = 0; c < 4; ++c) {
            const int kk = kd + c*16;
            if (kk < L_) {
                float v = a[r][c] * 0.125f;
                if (kk > q) v = NEGV;          // tril mask
                if (pm[kk] == 0.0f) v = NEGV;  // key mask
                v *= pq;                       // * padding_mask
                sc[q*L_ + kk] = v;
            }
        }
    }
}

// dst[i, d] = sum_j M[i, j] * src[j, d]  (+bias[i]) (+res[i,d]) (relu) (*pm[i])
// M: 50x50 smem, src/res/dst: L_ x LDX smem.
template<bool RELU>
__device__ __forceinline__ void mm_SM(float* __restrict__ dst,
                                      const float* __restrict__ M,
                                      const float* __restrict__ src,
                                      const float* __restrict__ res,
                                      const float* __restrict__ bias_g,
                                      const float* __restrict__ pm) {
    const int tid = threadIdx.x;
    const int d0 = tid & 15;
    const int g  = tid >> 4;
    int ib[4];
#pragma unroll
    for (int r = 0; r < 4; ++r) {
        int i = g + r*16; if (i >= L_) i = L_ - 1;
        ib[r] = i * L_;
    }
    float a[4][4] = {};
#pragma unroll 5
    for (int j = 0; j < L_; ++j) {
        float mv[4], sv[4];
#pragma unroll
        for (int r = 0; r < 4; ++r) mv[r] = M[ib[r] + j];
#pragma unroll
        for (int c = 0; c < 4; ++c) sv[c] = src[j*LDX + d0 + c*16];
#pragma unroll
        for (int r = 0; r < 4; ++r)
#pragma unroll
            for (int c = 0; c < 4; ++c) a[r][c] = fmaf(mv[r], sv[c], a[r][c]);
    }
#pragma unroll
    for (int r = 0; r < 4; ++r) {
        const int i = g + r*16;
        if (i >= L_) continue;
        const float bias = bias_g ? bias_g[i] : 0.0f;
        const float p    = pm ? pm[i] : 1.0f;
#pragma unroll
        for (int c = 0; c < 4; ++c) {
            const int d = d0 + c*16;
            float v = a[r][c] + bias;
            if (res)  v += res[i*LDX + d];
            if (RELU) v = fmaxf(v, 0.0f);
            v *= p;
            dst[i*LDX + d] = v;
        }
    }
}

__global__ void __launch_bounds__(TPB)
fissa_kernel(const int* __restrict__ ui, const int* __restrict__ pi,
             const int* __restrict__ ni, const float* __restrict__ pmask,
             const float* __restrict__ item_emb, const float* __restrict__ pos_emb,
             const float* __restrict__ Qs, const float* __restrict__ Ks,
             const float* __restrict__ Vs,
             const float* __restrict__ c1w, const float* __restrict__ c1b,
             const float* __restrict__ c2w, const float* __restrict__ c2b,
             const float* __restrict__ qitem,
             const float* __restrict__ Klba, const float* __restrict__ Vlba,
             const float* __restrict__ l1w, const float* __restrict__ l1b,
             const float* __restrict__ l2w, const float* __restrict__ l2b,
             const float* __restrict__ gw, const float* __restrict__ gb,
             float* __restrict__ out) {
    extern __shared__ float sm[];
    float* s_in  = sm + OFF_IN;
    float* s_x   = sm + OFF_X;
    float* t1    = sm + OFF_T1;
    float* t2    = sm + OFF_T2;
    float* s_w   = sm + OFF_W;
    float* s_sc  = sm + OFF_SC;
    float* s_pm  = sm + OFF_PM;
    float* s_g1  = sm + OFF_G1;
    float* s_glo = sm + OFF_GLO;
    float* s_gw  = sm + OFF_GW;

    const int b    = blockIdx.x;
    const int tid  = threadIdx.x;
    const int lane = tid & 31;
    const int wid  = tid >> 5;

    // ---- prologue: masks + gated_weight staging ----
    if (tid < 192) s_gw[tid] = gw[tid];
    if (tid < L_)  s_pm[tid] = pmask[b*L_ + tid];
    __syncthreads();

    // ---- gather + positional embedding + mask; also g1[l] = ie[l] . gw[0:64] ----
    for (int idx = tid; idx < L_*D_; idx += TPB) {
        const int l = idx >> 6, d = idx & 63;
        const int it = ui[b*L_ + l];
        s_in[l*LDX + d] = (item_emb[it*64 + d] + pos_emb[idx]) * s_pm[l];
    }
    for (int l = wid; l < L_; l += 8) {
        const int it = ui[b*L_ + l];
        float v = item_emb[it*64 + lane] * s_gw[lane]
                + item_emb[it*64 + lane + 32] * s_gw[lane + 32];
        v = warp_sum(v);
        if (lane == 0) s_g1[l] = v;
    }
    __syncthreads();
    ln_rows(s_in);                       // inputs = LN((ie + pos) * pm)
    __syncthreads();
    for (int idx = tid; idx < L_*LDX; idx += TPB) s_x[idx] = s_in[idx];
    __syncthreads();

    // ---- S self-attention blocks ----
    for (int s = 0; s < S_; ++s) {
        // Qx
        for (int i = tid; i < D_*D_; i += TPB) s_w[i] = Qs[s*D_*D_ + i];
        __syncthreads();
        mm_LW(t1, s_x, s_w);
        __syncthreads();
        // Kx
        for (int i = tid; i < D_*D_; i += TPB) s_w[i] = Ks[s*D_*D_ + i];
        __syncthreads();
        mm_LW(t2, s_x, s_w);
        __syncthreads();
        // stage V (doesn't conflict with scores' inputs) + scores
        for (int i = tid; i < D_*D_; i += TPB) s_w[i] = Vs[s*D_*D_ + i];
        mm_scores(s_sc, t1, t2, s_pm);
        __syncthreads();
        // Vx (Qx dead)
        mm_LW(t1, s_x, s_w);
        __syncthreads();
        // att = scores @ Vx + x  (Kx dead)
        mm_SM<false>(t2, s_sc, t1, s_x, nullptr, nullptr);
        __syncthreads();
        // stage c1 (scores dead) + LN(att)
        for (int i = tid; i < L_*L_; i += TPB) s_sc[i] = c1w[s*L_*L_ + i];
        ln_rows(t2);
        __syncthreads();
        // h = relu(c1 @ att + c1_b)
        mm_SM<true>(t1, s_sc, t2, nullptr, c1b + s*L_, nullptr);
        __syncthreads();
        // stage c2
        for (int i = tid; i < L_*L_; i += TPB) s_sc[i] = c2w[s*L_*L_ + i];
        __syncthreads();
        // ff = (c2 @ h + c2_b + att) * pm ; x = LN(ff)
        mm_SM<false>(s_x, s_sc, t1, t2, c2b + s*L_, s_pm);
        __syncthreads();
        ln_rows(s_x);
        __syncthreads();
    }
    // s_x = loc from here on (untouched below)

    // ---- LBA global attention on `inputs` ----
    for (int i = tid; i < D_*D_; i += TPB) s_w[i] = Klba[i];
    __syncthreads();
    mm_LW(t1, s_in, s_w);                // Kx
    __syncthreads();
    for (int i = tid; i < D_*D_; i += TPB) s_w[i] = Vlba[i];
    __syncthreads();
    mm_LW(t2, s_in, s_w);                // Vx
    __syncthreads();
    // sc[l] = q . Kx[l]  (+ key mask)
    for (int l = wid; l < L_; l += 8) {
        float v = qitem[lane] * t1[l*LDX + lane]
                + qitem[lane + 32] * t1[l*LDX + lane + 32];
        v = warp_sum(v);
        if (lane == 0) s_sc[l] = (s_pm[l] == 0.0f) ? NEGV : v;
    }
    __syncthreads();
    // softmax over 50 (warp 0)
    if (wid == 0) {
        float v0 = (lane < L_) ? s_sc[lane] : -3.0e38f;
        float v1 = (lane + 32 < L_) ? s_sc[lane + 32] : -3.0e38f;
        float m = warp_max(fmaxf(v0, v1));
        float e0 = (lane < L_) ? expf(v0 - m) : 0.0f;
        float e1 = (lane + 32 < L_) ? expf(v1 - m) : 0.0f;
        float ssum = warp_sum(e0 + e1);
        if (lane < L_)      s_sc[lane]      = e0 / ssum;
        if (lane + 32 < L_) s_sc[lane + 32] = e1 / ssum;
    }
    __syncthreads();
    // glo[d] = sum_l sc[l] * Vx[l, d]
    if (tid < D_) {
        float a = 0.0f;
        for (int l = 0; l < L_; ++l) a = fmaf(s_sc[l], t2[l*LDX + tid], a);
        s_glo[tid] = a;
    }
    __syncthreads();
    // LN -> l1/l2 residual -> LN -> gglo scalar (warp 0)
    if (wid == 0) {
        float v0 = s_glo[lane], v1 = s_glo[lane + 32];
        float mean = warp_sum(v0 + v1) * (1.0f/64.0f);
        float d0 = v0 - mean, d1 = v1 - mean;
        float var = warp_sum(d0*d0 + d1*d1) * (1.0f/64.0f);
        float inv = rsqrtf(var + 1e-8f);
        float g0 = d0 * inv, g1v = d1 * inv;
        const float w1 = l1w[0], bb1 = l1b[0], w2 = l2w[0], bb2 = l2b[0];
        float h0 = fmaxf(w1*g0 + bb1, 0.0f);
        float h1 = fmaxf(w1*g1v + bb1, 0.0f);
        g0  = w2*h0 + bb2 + g0;
        g1v = w2*h1 + bb2 + g1v;
        mean = warp_sum(g0 + g1v) * (1.0f/64.0f);
        d0 = g0 - mean; d1 = g1v - mean;
        var = warp_sum(d0*d0 + d1*d1) * (1.0f/64.0f);
        inv = rsqrtf(var + 1e-8f);
        g0 = d0 * inv; g1v = d1 * inv;
        s_glo[lane] = g0; s_glo[lane + 32] = g1v;
        float gg = warp_sum(g0 * s_gw[64 + lane] + g1v * s_gw[96 + lane]);
        if (lane == 0) s_gw[192] = gg;   // glo . gw[64:128]
    }
    __syncthreads();

    // ---- gated fusion + final LN + pos/neg dots ----
    const float gbias = gb[0];
    for (int t = wid; t < 2*L_; t += 8) {
        const int pn = (t >= L_);
        const int l  = t - pn*L_;
        const int*  items = pn ? ni : pi;
        const int   it = items[b*L_ + l];
        const float e0 = item_emb[it*64 + lane];
        const float e1 = item_emb[it*64 + lane + 32];
        const float dot3 = warp_sum(e0 * s_gw[128 + lane] + e1 * s_gw[160 + lane]);
        const float logit = s_g1[l] + s_gw[192] + dot3 + gbias;
        const float g = sigmoidf_(sigmoidf_(logit));
        float o0 = (s_x[l*LDX + lane]      * g + s_glo[lane]      * (1.0f - g)) * s_pm[l];
        float o1 = (s_x[l*LDX + lane + 32] * g + s_glo[lane + 32] * (1.0f - g)) * s_pm[l];
        const float mean = warp_sum(o0 + o1) * (1.0f/64.0f);
        const float d0 = o0 - mean, d1 = o1 - mean;
        const float var = warp_sum(d0*d0 + d1*d1) * (1.0f/64.0f);
        const float inv = rsqrtf(var + 1e-8f);
        const float r = warp_sum(d0*inv*e0 + d1*inv*e1);
        if (lane == 0) out[pn*B_*L_ + b*L_ + l] = r;
    }
}

extern "C" void kernel_launch(void* const* d_in, const int* in_sizes, int n_in,
                              void* d_out, int out_size) {
    const int*   ui       = (const int*)  d_in[0];
    const int*   pi       = (const int*)  d_in[1];
    const int*   ni       = (const int*)  d_in[2];
    const float* pmask    = (const float*)d_in[3];
    const float* item_emb = (const float*)d_in[4];
    const float* pos_emb  = (const float*)d_in[5];
    const float* Qs       = (const float*)d_in[6];
    const float* Ks       = (const float*)d_in[7];
    const float* Vs       = (const float*)d_in[8];
    const float* c1w      = (const float*)d_in[9];
    const float* c1b      = (const float*)d_in[10];
    const float* c2w      = (const float*)d_in[11];
    const float* c2b      = (const float*)d_in[12];
    const float* qitem    = (const float*)d_in[13];
    const float* Klba     = (const float*)d_in[14];
    const float* Vlba     = (const float*)d_in[15];
    const float* l1w      = (const float*)d_in[16];
    const float* l1b      = (const float*)d_in[17];
    const float* l2w      = (const float*)d_in[18];
    const float* l2b      = (const float*)d_in[19];
    const float* gw       = (const float*)d_in[20];
    const float* gb       = (const float*)d_in[21];
    float* out = (float*)d_out;

    cudaFuncSetAttribute(fissa_kernel,
                         cudaFuncAttributeMaxDynamicSharedMemorySize, SMEM_BYTES);
    fissa_kernel<<<B_, TPB, SMEM_BYTES>>>(ui, pi, ni, pmask, item_emb, pos_emb,
                                          Qs, Ks, Vs, c1w, c1b, c2w, c2b, qitem,
                                          Klba, Vlba, l1w, l1b, l2w, l2b, gw, gb,
                                          out);
}

// round 5
// speedup vs baseline: 1.2311x; 1.2311x over previous
#include <cuda_runtime.h>
#include <math.h>

#define B_    1024
#define L_    50
#define D_    64
#define S_    2
#define LDX   68          // tile row stride (mult of 4 -> float4-aligned rows)
#define LDM   52          // scores / c-weight row stride (mult of 4)
#define TPB   256
#define NEGV  (-4294967295.0f)

// ---- shared memory layout (floats) ----
#define OFF_IN   0                        // inputs (post first LN), kept for LBA
#define OFF_X    (OFF_IN + L_*LDX)        // running x
#define OFF_T1   (OFF_X  + L_*LDX)        // temp tile 1
#define OFF_T2   (OFF_T1 + L_*LDX)        // temp tile 2
#define OFF_W    (OFF_T2 + L_*LDX)        // 64x64 weight staging
#define OFF_SC   (OFF_W  + D_*D_)         // 50x52 scores / c1 / c2
#define OFF_PM   (OFF_SC + L_*LDM)        // padding mask (50)
#define OFF_G1   (OFF_PM + 64)            // ie . gw[0:64] per position
#define OFF_GLO  (OFF_G1 + 64)            // glo vector (64)
#define OFF_GW   (OFF_GLO + 64)           // gated_weight (192) + gglo scalar @192
#define SMEM_F   (OFF_GW + 200)
#define SMEM_BYTES (SMEM_F * 4)

__device__ __forceinline__ float warp_sum(float v) {
#pragma unroll
    for (int o = 16; o; o >>= 1) v += __shfl_xor_sync(0xffffffffu, v, o);
    return v;
}
__device__ __forceinline__ float warp_max(float v) {
#pragma unroll
    for (int o = 16; o; o >>= 1) v = fmaxf(v, __shfl_xor_sync(0xffffffffu, v, o));
    return v;
}
__device__ __forceinline__ float sigmoidf_(float x) {
    return 1.0f / (1.0f + expf(-x));
}

// LayerNorm over D=64 for each of L_ rows (warp per row), in place.
__device__ __forceinline__ void ln_rows(float* p) {
    const int lane = threadIdx.x & 31, wid = threadIdx.x >> 5;
    for (int l = wid; l < L_; l += 8) {
        float v0 = p[l*LDX + lane], v1 = p[l*LDX + lane + 32];
        float mean = warp_sum(v0 + v1) * (1.0f/64.0f);
        float d0 = v0 - mean, d1 = v1 - mean;
        float var = warp_sum(d0*d0 + d1*d1) * (1.0f/64.0f);
        float inv = rsqrtf(var + 1e-8f);
        p[l*LDX + lane]      = d0 * inv;
        p[l*LDX + lane + 32] = d1 * inv;
    }
}

// dst[l, d] = sum_k src[l, k] * W[k, d]   (src: L_ x LDX smem, W: 64x64 smem)
// Thread owns 4 rows (g+16r) x 4 consecutive d (4*(tid&15)..+3). All smem
// traffic is LDS.128: per 4-k block, 4 x-vec loads + 4 w-vec loads feed 64 FMA.
__device__ __forceinline__ void mm_LW(float* __restrict__ dst,
                                      const float* __restrict__ src,
                                      const float* __restrict__ W) {
    const int tid = threadIdx.x;
    const int d4 = (tid & 15) * 4;
    const int g  = tid >> 4;
    int rb[4];
#pragma unroll
    for (int r = 0; r < 4; ++r) {
        int l = g + r*16; if (l >= L_) l = L_ - 1;
        rb[r] = l * LDX;
    }
    float a[4][4] = {};
#pragma unroll
    for (int k = 0; k < D_; k += 4) {
        float4 xv[4];
#pragma unroll
        for (int r = 0; r < 4; ++r) xv[r] = *(const float4*)&src[rb[r] + k];
#pragma unroll
        for (int kk = 0; kk < 4; ++kk) {
            const float4 w = *(const float4*)&W[(k + kk)*D_ + d4];
#pragma unroll
            for (int r = 0; r < 4; ++r) {
                const float x = ((const float*)&xv[r])[kk];
                a[r][0] = fmaf(x, w.x, a[r][0]);
                a[r][1] = fmaf(x, w.y, a[r][1]);
                a[r][2] = fmaf(x, w.z, a[r][2]);
                a[r][3] = fmaf(x, w.w, a[r][3]);
            }
        }
    }
#pragma unroll
    for (int r = 0; r < 4; ++r) {
        const int l = g + r*16;
        if (l < L_)
            *(float4*)&dst[l*LDX + d4] = make_float4(a[r][0], a[r][1], a[r][2], a[r][3]);
    }
}

// scores[q, k] = (Q[q,:] . K[k,:]) / 8, then tril/keymask NEG fill, then * pm[q]
// Vectorized along d (float4 on both operands).
__device__ __forceinline__ void mm_scores(float* __restrict__ sc,
                                          const float* __restrict__ Q,
                                          const float* __restrict__ Kx,
                                          const float* __restrict__ pm) {
    const int tid = threadIdx.x;
    const int kd = tid & 15;
    const int g  = tid >> 4;
    int qb[4], kb[4];
#pragma unroll
    for (int r = 0; r < 4; ++r) {
        int q = g + r*16; if (q >= L_) q = L_ - 1;
        qb[r] = q * LDX;
    }
#pragma unroll
    for (int c = 0; c < 4; ++c) {
        int kk = kd + c*16; if (kk >= L_) kk = L_ - 1;
        kb[c] = kk * LDX;
    }
    float a[4][4] = {};
#pragma unroll
    for (int d = 0; d < D_; d += 4) {
        float4 qv[4], kv[4];
#pragma unroll
        for (int r = 0; r < 4; ++r) qv[r] = *(const float4*)&Q[qb[r] + d];
#pragma unroll
        for (int c = 0; c < 4; ++c) kv[c] = *(const float4*)&Kx[kb[c] + d];
#pragma unroll
        for (int r = 0; r < 4; ++r)
#pragma unroll
            for (int c = 0; c < 4; ++c) {
                float t;
                t = fmaf(qv[r].x, kv[c].x, a[r][c]);
                t = fmaf(qv[r].y, kv[c].y, t);
                t = fmaf(qv[r].z, kv[c].z, t);
                a[r][c] = fmaf(qv[r].w, kv[c].w, t);
            }
    }
#pragma unroll
    for (int r = 0; r < 4; ++r) {
        const int q = g + r*16;
        if (q >= L_) continue;
        const float pq = pm[q];
#pragma unroll
        for (int c = 0; c < 4; ++c) {
            const int kk = kd + c*16;
            if (kk < L_) {
                float v = a[r][c] * 0.125f;
                if (kk > q) v = NEGV;          // tril mask
                if (pm[kk] == 0.0f) v = NEGV;  // key mask
                v *= pq;                       // * padding_mask
                sc[q*LDM + kk] = v;
            }
        }
    }
}

// dst[i, d] = sum_j M[i, j] * src[j, d]  (+bias[i]) (+res[i,d]) (relu) (*pm[i])
// M: 50 x LDM smem, src/res/dst: L_ x LDX smem. Vectorized along j and d.
template<bool RELU>
__device__ __forceinline__ void mm_SM(float* __restrict__ dst,
                                      const float* __restrict__ M,
                                      const float* __restrict__ src,
                                      const float* __restrict__ res,
                                      const float* __restrict__ bias_g,
                                      const float* __restrict__ pm) {
    const int tid = threadIdx.x;
    const int d4 = (tid & 15) * 4;
    const int g  = tid >> 4;
    int ib[4];
#pragma unroll
    for (int r = 0; r < 4; ++r) {
        int i = g + r*16; if (i >= L_) i = L_ - 1;
        ib[r] = i * LDM;
    }
    float a[4][4] = {};
#pragma unroll
    for (int j = 0; j < 48; j += 4) {
        float4 mv[4], sv[4];
#pragma unroll
        for (int r = 0; r < 4; ++r) mv[r] = *(const float4*)&M[ib[r] + j];
#pragma unroll
        for (int jj = 0; jj < 4; ++jj) sv[jj] = *(const float4*)&src[(j + jj)*LDX + d4];
#pragma unroll
        for (int jj = 0; jj < 4; ++jj)
#pragma unroll
            for (int r = 0; r < 4; ++r) {
                const float m = ((const float*)&mv[r])[jj];
                a[r][0] = fmaf(m, sv[jj].x, a[r][0]);
                a[r][1] = fmaf(m, sv[jj].y, a[r][1]);
                a[r][2] = fmaf(m, sv[jj].z, a[r][2]);
                a[r][3] = fmaf(m, sv[jj].w, a[r][3]);
            }
    }
    // tail j = 48, 49
#pragma unroll
    for (int j = 48; j < L_; ++j) {
        const float4 sv = *(const float4*)&src[j*LDX + d4];
#pragma unroll
        for (int r = 0; r < 4; ++r) {
            const float m = M[ib[r] + j];
            a[r][0] = fmaf(m, sv.x, a[r][0]);
            a[r][1] = fmaf(m, sv.y, a[r][1]);
            a[r][2] = fmaf(m, sv.z, a[r][2]);
            a[r][3] = fmaf(m, sv.w, a[r][3]);
        }
    }
#pragma unroll
    for (int r = 0; r < 4; ++r) {
        const int i = g + r*16;
        if (i >= L_) continue;
        const float bias = bias_g ? bias_g[i] : 0.0f;
        const float p    = pm ? pm[i] : 1.0f;
        float4 o;
        float* ov = (float*)&o;
#pragma unroll
        for (int c = 0; c < 4; ++c) {
            float v = a[r][c] + bias;
            if (res)  v += res[i*LDX + d4 + c];
            if (RELU) v = fmaxf(v, 0.0f);
            ov[c] = v * p;
        }
        *(float4*)&dst[i*LDX + d4] = o;
    }
}

__global__ void __launch_bounds__(TPB)
fissa_kernel(const int* __restrict__ ui, const int* __restrict__ pi,
             const int* __restrict__ ni, const float* __restrict__ pmask,
             const float* __restrict__ item_emb, const float* __restrict__ pos_emb,
             const float* __restrict__ Qs, const float* __restrict__ Ks,
             const float* __restrict__ Vs,
             const float* __restrict__ c1w, const float* __restrict__ c1b,
             const float* __restrict__ c2w, const float* __restrict__ c2b,
             const float* __restrict__ qitem,
             const float* __restrict__ Klba, const float* __restrict__ Vlba,
             const float* __restrict__ l1w, const float* __restrict__ l1b,
             const float* __restrict__ l2w, const float* __restrict__ l2b,
             const float* __restrict__ gw, const float* __restrict__ gb,
             float* __restrict__ out) {
    extern __shared__ float sm[];
    float* s_in  = sm + OFF_IN;
    float* s_x   = sm + OFF_X;
    float* t1    = sm + OFF_T1;
    float* t2    = sm + OFF_T2;
    float* s_w   = sm + OFF_W;
    float* s_sc  = sm + OFF_SC;
    float* s_pm  = sm + OFF_PM;
    float* s_g1  = sm + OFF_G1;
    float* s_glo = sm + OFF_GLO;
    float* s_gw  = sm + OFF_GW;

    const int b    = blockIdx.x;
    const int tid  = threadIdx.x;
    const int lane = tid & 31;
    const int wid  = tid >> 5;

    // ---- prologue: masks + gated_weight staging ----
    if (tid < 192) s_gw[tid] = gw[tid];
    if (tid < L_)  s_pm[tid] = pmask[b*L_ + tid];
    __syncthreads();

    // ---- gather + positional embedding + mask; also g1[l] = ie[l] . gw[0:64] ----
    for (int idx = tid; idx < L_*16; idx += TPB) {
        const int l = idx >> 4, c4 = (idx & 15) * 4;
        const int it = ui[b*L_ + l];
        const float4 e = *(const float4*)&item_emb[it*D_ + c4];
        const float4 pe = *(const float4*)&pos_emb[l*D_ + c4];
        const float p = s_pm[l];
        float4 o = make_float4((e.x+pe.x)*p, (e.y+pe.y)*p, (e.z+pe.z)*p, (e.w+pe.w)*p);
        *(float4*)&s_in[l*LDX + c4] = o;
    }
    for (int l = wid; l < L_; l += 8) {
        const int it = ui[b*L_ + l];
        float v = item_emb[it*D_ + lane] * s_gw[lane]
                + item_emb[it*D_ + lane + 32] * s_gw[lane + 32];
        v = warp_sum(v);
        if (lane == 0) s_g1[l] = v;
    }
    __syncthreads();
    ln_rows(s_in);                       // inputs = LN((ie + pos) * pm)
    __syncthreads();
    for (int idx = tid; idx < L_*17; idx += TPB)
        ((float4*)s_x)[idx] = ((const float4*)s_in)[idx];
    __syncthreads();

    // ---- S self-attention blocks ----
    for (int s = 0; s < S_; ++s) {
        // Qx
        for (int i = tid; i < D_*D_/4; i += TPB)
            ((float4*)s_w)[i] = ((const float4*)(Qs + s*D_*D_))[i];
        __syncthreads();
        mm_LW(t1, s_x, s_w);
        __syncthreads();
        // Kx
        for (int i = tid; i < D_*D_/4; i += TPB)
            ((float4*)s_w)[i] = ((const float4*)(Ks + s*D_*D_))[i];
        __syncthreads();
        mm_LW(t2, s_x, s_w);
        __syncthreads();
        // stage V (doesn't conflict with scores' inputs) + scores
        for (int i = tid; i < D_*D_/4; i += TPB)
            ((float4*)s_w)[i] = ((const float4*)(Vs + s*D_*D_))[i];
        mm_scores(s_sc, t1, t2, s_pm);
        __syncthreads();
        // Vx (Qx dead)
        mm_LW(t1, s_x, s_w);
        __syncthreads();
        // att = scores @ Vx + x  (Kx dead)
        mm_SM<false>(t2, s_sc, t1, s_x, nullptr, nullptr);
        __syncthreads();
        // stage c1 (scores dead) + LN(att)
        for (int idx = tid; idx < L_*L_; idx += TPB) {
            const int i = idx / L_, j = idx - i*L_;
            s_sc[i*LDM + j] = c1w[s*L_*L_ + idx];
        }
        ln_rows(t2);
        __syncthreads();
        // h = relu(c1 @ att + c1_b)
        mm_SM<true>(t1, s_sc, t2, nullptr, c1b + s*L_, nullptr);
        __syncthreads();
        // stage c2
        for (int idx = tid; idx < L_*L_; idx += TPB) {
            const int i = idx / L_, j = idx - i*L_;
            s_sc[i*LDM + j] = c2w[s*L_*L_ + idx];
        }
        __syncthreads();
        // ff = (c2 @ h + c2_b + att) * pm ; x = LN(ff)
        mm_SM<false>(s_x, s_sc, t1, t2, c2b + s*L_, s_pm);
        __syncthreads();
        ln_rows(s_x);
        __syncthreads();
    }
    // s_x = loc from here on (untouched below)

    // ---- LBA global attention on `inputs` ----
    for (int i = tid; i < D_*D_/4; i += TPB)
        ((float4*)s_w)[i] = ((const float4*)Klba)[i];
    __syncthreads();
    mm_LW(t1, s_in, s_w);                // Kx
    __syncthreads();
    for (int i = tid; i < D_*D_/4; i += TPB)
        ((float4*)s_w)[i] = ((const float4*)Vlba)[i];
    __syncthreads();
    mm_LW(t2, s_in, s_w);                // Vx
    __syncthreads();
    // sc[l] = q . Kx[l]  (+ key mask)
    for (int l = wid; l < L_; l += 8) {
        float v = qitem[lane] * t1[l*LDX + lane]
                + qitem[lane + 32] * t1[l*LDX + lane + 32];
        v = warp_sum(v);
        if (lane == 0) s_sc[l] = (s_pm[l] == 0.0f) ? NEGV : v;
    }
    __syncthreads();
    // softmax over 50 (warp 0)
    if (wid == 0) {
        float v0 = (lane < L_) ? s_sc[lane] : -3.0e38f;
        float v1 = (lane + 32 < L_) ? s_sc[lane + 32] : -3.0e38f;
        float m = warp_max(fmaxf(v0, v1));
        float e0 = (lane < L_) ? expf(v0 - m) : 0.0f;
        float e1 = (lane + 32 < L_) ? expf(v1 - m) : 0.0f;
        float ssum = warp_sum(e0 + e1);
        if (lane < L_)      s_sc[lane]      = e0 / ssum;
        if (lane + 32 < L_) s_sc[lane + 32] = e1 / ssum;
    }
    __syncthreads();
    // glo[d] = sum_l sc[l] * Vx[l, d]
    if (tid < D_) {
        float a = 0.0f;
        for (int l = 0; l < L_; ++l) a = fmaf(s_sc[l], t2[l*LDX + tid], a);
        s_glo[tid] = a;
    }
    __syncthreads();
    // LN -> l1/l2 residual -> LN -> gglo scalar (warp 0)
    if (wid == 0) {
        float v0 = s_glo[lane], v1 = s_glo[lane + 32];
        float mean = warp_sum(v0 + v1) * (1.0f/64.0f);
        float d0 = v0 - mean, d1 = v1 - mean;
        float var = warp_sum(d0*d0 + d1*d1) * (1.0f/64.0f);
        float inv = rsqrtf(var + 1e-8f);
        float g0 = d0 * inv, g1v = d1 * inv;
        const float w1 = l1w[0], bb1 = l1b[0], w2 = l2w[0], bb2 = l2b[0];
        float h0 = fmaxf(w1*g0 + bb1, 0.0f);
        float h1 = fmaxf(w1*g1v + bb1, 0.0f);
        g0  = w2*h0 + bb2 + g0;
        g1v = w2*h1 + bb2 + g1v;
        mean = warp_sum(g0 + g1v) * (1.0f/64.0f);
        d0 = g0 - mean; d1 = g1v - mean;
        var = warp_sum(d0*d0 + d1*d1) * (1.0f/64.0f);
        inv = rsqrtf(var + 1e-8f);
        g0 = d0 * inv; g1v = d1 * inv;
        s_glo[lane] = g0; s_glo[lane + 32] = g1v;
        float gg = warp_sum(g0 * s_gw[64 + lane] + g1v * s_gw[96 + lane]);
        if (lane == 0) s_gw[192] = gg;   // glo . gw[64:128]
    }
    __syncthreads();

    // ---- gated fusion + final LN + pos/neg dots ----
    const float gbias = gb[0];
    for (int t = wid; t < 2*L_; t += 8) {
        const int pn = (t >= L_);
        const int l  = t - pn*L_;
        const int*  items = pn ? ni : pi;
        const int   it = items[b*L_ + l];
        const float e0 = item_emb[it*D_ + lane];
        const float e1 = item_emb[it*D_ + lane + 32];
        const float dot3 = warp_sum(e0 * s_gw[128 + lane] + e1 * s_gw[160 + lane]);
        const float logit = s_g1[l] + s_gw[192] + dot3 + gbias;
        const float g = sigmoidf_(sigmoidf_(logit));
        float o0 = (s_x[l*LDX + lane]      * g + s_glo[lane]      * (1.0f - g)) * s_pm[l];
        float o1 = (s_x[l*LDX + lane + 32] * g + s_glo[lane + 32] * (1.0f - g)) * s_pm[l];
        const float mean = warp_sum(o0 + o1) * (1.0f/64.0f);
        const float d0 = o0 - mean, d1 = o1 - mean;
        const float var = warp_sum(d0*d0 + d1*d1) * (1.0f/64.0f);
        const float inv = rsqrtf(var + 1e-8f);
        const float r = warp_sum(d0*inv*e0 + d1*inv*e1);
        if (lane == 0) out[pn*B_*L_ + b*L_ + l] = r;
    }
}

extern "C" void kernel_launch(void* const* d_in, const int* in_sizes, int n_in,
                              void* d_out, int out_size) {
    const int*   ui       = (const int*)  d_in[0];
    const int*   pi       = (const int*)  d_in[1];
    const int*   ni       = (const int*)  d_in[2];
    const float* pmask    = (const float*)d_in[3];
    const float* item_emb = (const float*)d_in[4];
    const float* pos_emb  = (const float*)d_in[5];
    const float* Qs       = (const float*)d_in[6];
    const float* Ks       = (const float*)d_in[7];
    const float* Vs       = (const float*)d_in[8];
    const float* c1w      = (const float*)d_in[9];
    const float* c1b      = (const float*)d_in[10];
    const float* c2w      = (const float*)d_in[11];
    const float* c2b      = (const float*)d_in[12];
    const float* qitem    = (const float*)d_in[13];
    const float* Klba     = (const float*)d_in[14];
    const float* Vlba     = (const float*)d_in[15];
    const float* l1w      = (const float*)d_in[16];
    const float* l1b      = (const float*)d_in[17];
    const float* l2w      = (const float*)d_in[18];
    const float* l2b      = (const float*)d_in[19];
    const float* gw       = (const float*)d_in[20];
    const float* gb       = (const float*)d_in[21];
    float* out = (float*)d_out;

    cudaFuncSetAttribute(fissa_kernel,
                         cudaFuncAttributeMaxDynamicSharedMemorySize, SMEM_BYTES);
    fissa_kernel<<<B_, TPB, SMEM_BYTES>>>(ui, pi, ni, pmask, item_emb, pos_emb,
                                          Qs, Ks, Vs, c1w, c1b, c2w, c2b, qitem,
                                          Klba, Vlba, l1w, l1b, l2w, l2b, gw, gb,
                                          out);
}

// round 6
// speedup vs baseline: 1.7450x; 1.4174x over previous
#include <cuda_runtime.h>
#include <math.h>

#define B_    1024
#define L_    50
#define D_    64
#define S_    2
#define LDX   68          // tile row stride (mult of 4 -> float4-aligned rows)
#define LDM   52          // scores / c-weight row stride (mult of 4)
#define TPB   256
#define NEGV  (-4294967295.0f)

// ---- shared memory layout (floats) ----
#define OFF_X    0                        // running x (starts as `inputs`, ends as loc)
#define OFF_T1   (OFF_X  + L_*LDX)        // temp tile 1
#define OFF_T2   (OFF_T1 + L_*LDX)        // temp tile 2
#define OFF_SC   (OFF_T2 + L_*LDX)        // 50x52 scores / c1 / c2 / epilogue scratch
#define OFF_PM   (OFF_SC + L_*LDM)        // padding mask (50)
#define OFF_G1   (OFF_PM + 64)            // ie . gw[0:64] per position
#define OFF_GLO  (OFF_G1 + 64)            // glo vector (64)
#define OFF_GW   (OFF_GLO + 64)           // gated_weight (192) + gglo scalar @192
#define SMEM_F   (OFF_GW + 200)
#define SMEM_BYTES (SMEM_F * 4)           // 52768 B -> 4 CTAs/SM

__device__ __forceinline__ float warp_sum(float v) {
#pragma unroll
    for (int o = 16; o; o >>= 1) v += __shfl_xor_sync(0xffffffffu, v, o);
    return v;
}
__device__ __forceinline__ float warp_max(float v) {
#pragma unroll
    for (int o = 16; o; o >>= 1) v = fmaxf(v, __shfl_xor_sync(0xffffffffu, v, o));
    return v;
}
__device__ __forceinline__ float sigmoidf_(float x) {
    return 1.0f / (1.0f + expf(-x));
}

// LayerNorm over D=64 for each of L_ rows (warp per row), in place.
__device__ __forceinline__ void ln_rows(float* p) {
    const int lane = threadIdx.x & 31, wid = threadIdx.x >> 5;
    for (int l = wid; l < L_; l += 8) {
        float v0 = p[l*LDX + lane], v1 = p[l*LDX + lane + 32];
        float mean = warp_sum(v0 + v1) * (1.0f/64.0f);
        float d0 = v0 - mean, d1 = v1 - mean;
        float var = warp_sum(d0*d0 + d1*d1) * (1.0f/64.0f);
        float inv = rsqrtf(var + 1e-8f);
        p[l*LDX + lane]      = d0 * inv;
        p[l*LDX + lane + 32] = d1 * inv;
    }
}

// dst[l, d] = sum_k src[l, k] * W[k, d]
// src: L_ x LDX smem; W: 64x64 GLOBAL (L1/L2-resident, broadcast across warp).
__device__ __forceinline__ void mm_LW(float* __restrict__ dst,
                                      const float* __restrict__ src,
                                      const float* __restrict__ Wg) {
    const int tid = threadIdx.x;
    const int d4 = (tid & 15) * 4;
    const int g  = tid >> 4;
    int rb[4];
#pragma unroll
    for (int r = 0; r < 4; ++r) {
        int l = g + r*16; if (l >= L_) l = L_ - 1;
        rb[r] = l * LDX;
    }
    float a[4][4] = {};
#pragma unroll
    for (int k = 0; k < D_; k += 4) {
        float4 xv[4];
#pragma unroll
        for (int r = 0; r < 4; ++r) xv[r] = *(const float4*)&src[rb[r] + k];
#pragma unroll
        for (int kk = 0; kk < 4; ++kk) {
            const float4 w = __ldg((const float4*)&Wg[(k + kk)*D_ + d4]);
#pragma unroll
            for (int r = 0; r < 4; ++r) {
                const float x = ((const float*)&xv[r])[kk];
                a[r][0] = fmaf(x, w.x, a[r][0]);
                a[r][1] = fmaf(x, w.y, a[r][1]);
                a[r][2] = fmaf(x, w.z, a[r][2]);
                a[r][3] = fmaf(x, w.w, a[r][3]);
            }
        }
    }
#pragma unroll
    for (int r = 0; r < 4; ++r) {
        const int l = g + r*16;
        if (l < L_)
            *(float4*)&dst[l*LDX + d4] = make_float4(a[r][0], a[r][1], a[r][2], a[r][3]);
    }
}

// scores[q, k] = (Q[q,:] . K[k,:]) / 8, then tril/keymask NEG fill, then * pm[q]
__device__ __forceinline__ void mm_scores(float* __restrict__ sc,
                                          const float* __restrict__ Q,
                                          const float* __restrict__ Kx,
                                          const float* __restrict__ pm) {
    const int tid = threadIdx.x;
    const int kd = tid & 15;
    const int g  = tid >> 4;
    int qb[4], kb[4];
#pragma unroll
    for (int r = 0; r < 4; ++r) {
        int q = g + r*16; if (q >= L_) q = L_ - 1;
        qb[r] = q * LDX;
    }
#pragma unroll
    for (int c = 0; c < 4; ++c) {
        int kk = kd + c*16; if (kk >= L_) kk = L_ - 1;
        kb[c] = kk * LDX;
    }
    float a[4][4] = {};
#pragma unroll
    for (int d = 0; d < D_; d += 4) {
        float4 qv[4], kv[4];
#pragma unroll
        for (int r = 0; r < 4; ++r) qv[r] = *(const float4*)&Q[qb[r] + d];
#pragma unroll
        for (int c = 0; c < 4; ++c) kv[c] = *(const float4*)&Kx[kb[c] + d];
#pragma unroll
        for (int r = 0; r < 4; ++r)
#pragma unroll
            for (int c = 0; c < 4; ++c) {
                float t;
                t = fmaf(qv[r].x, kv[c].x, a[r][c]);
                t = fmaf(qv[r].y, kv[c].y, t);
                t = fmaf(qv[r].z, kv[c].z, t);
                a[r][c] = fmaf(qv[r].w, kv[c].w, t);
            }
    }
#pragma unroll
    for (int r = 0; r < 4; ++r) {
        const int q = g + r*16;
        if (q >= L_) continue;
        const float pq = pm[q];
#pragma unroll
        for (int c = 0; c < 4; ++c) {
            const int kk = kd + c*16;
            if (kk < L_) {
                float v = a[r][c] * 0.125f;
                if (kk > q) v = NEGV;          // tril mask
                if (pm[kk] == 0.0f) v = NEGV;  // key mask
                v *= pq;                       // * padding_mask
                sc[q*LDM + kk] = v;
            }
        }
    }
}

// dst[i, d] = sum_j M[i, j] * src[j, d]  (+bias[i]) (+res[i,d]) (relu) (*pm[i])
// M: 50 x LDM smem, src/res/dst: L_ x LDX smem.
template<bool RELU>
__device__ __forceinline__ void mm_SM(float* __restrict__ dst,
                                      const float* __restrict__ M,
                                      const float* __restrict__ src,
                                      const float* __restrict__ res,
                                      const float* __restrict__ bias_g,
                                      const float* __restrict__ pm) {
    const int tid = threadIdx.x;
    const int d4 = (tid & 15) * 4;
    const int g  = tid >> 4;
    int ib[4];
#pragma unroll
    for (int r = 0; r < 4; ++r) {
        int i = g + r*16; if (i >= L_) i = L_ - 1;
        ib[r] = i * LDM;
    }
    float a[4][4] = {};
#pragma unroll
    for (int j = 0; j < 48; j += 4) {
        float4 mv[4], sv[4];
#pragma unroll
        for (int r = 0; r < 4; ++r) mv[r] = *(const float4*)&M[ib[r] + j];
#pragma unroll
        for (int jj = 0; jj < 4; ++jj) sv[jj] = *(const float4*)&src[(j + jj)*LDX + d4];
#pragma unroll
        for (int jj = 0; jj < 4; ++jj)
#pragma unroll
            for (int r = 0; r < 4; ++r) {
                const float m = ((const float*)&mv[r])[jj];
                a[r][0] = fmaf(m, sv[jj].x, a[r][0]);
                a[r][1] = fmaf(m, sv[jj].y, a[r][1]);
                a[r][2] = fmaf(m, sv[jj].z, a[r][2]);
                a[r][3] = fmaf(m, sv[jj].w, a[r][3]);
            }
    }
#pragma unroll
    for (int j = 48; j < L_; ++j) {
        const float4 sv = *(const float4*)&src[j*LDX + d4];
#pragma unroll
        for (int r = 0; r < 4; ++r) {
            const float m = M[ib[r] + j];
            a[r][0] = fmaf(m, sv.x, a[r][0]);
            a[r][1] = fmaf(m, sv.y, a[r][1]);
            a[r][2] = fmaf(m, sv.z, a[r][2]);
            a[r][3] = fmaf(m, sv.w, a[r][3]);
        }
    }
#pragma unroll
    for (int r = 0; r < 4; ++r) {
        const int i = g + r*16;
        if (i >= L_) continue;
        const float bias = bias_g ? bias_g[i] : 0.0f;
        const float p    = pm ? pm[i] : 1.0f;
        float4 o;
        float* ov = (float*)&o;
        if (res) {
            const float4 rv = *(const float4*)&res[i*LDX + d4];
            const float* rp = (const float*)&rv;
#pragma unroll
            for (int c = 0; c < 4; ++c) {
                float v = a[r][c] + bias + rp[c];
                if (RELU) v = fmaxf(v, 0.0f);
                ov[c] = v * p;
            }
        } else {
#pragma unroll
            for (int c = 0; c < 4; ++c) {
                float v = a[r][c] + bias;
                if (RELU) v = fmaxf(v, 0.0f);
                ov[c] = v * p;
            }
        }
        *(float4*)&dst[i*LDX + d4] = o;
    }
}

// gather + positional embedding + mask into dst (L_ x LDX), no LN.
__device__ __forceinline__ void build_inputs(float* __restrict__ dst,
                                             const int* __restrict__ ui_row,
                                             const float* __restrict__ item_emb,
                                             const float* __restrict__ pos_emb,
                                             const float* __restrict__ pm) {
    const int tid = threadIdx.x;
    for (int idx = tid; idx < L_*16; idx += TPB) {
        const int l = idx >> 4, c4 = (idx & 15) * 4;
        const int it = __ldg(&ui_row[l]);
        const float4 e  = __ldg((const float4*)&item_emb[it*D_ + c4]);
        const float4 pe = __ldg((const float4*)&pos_emb[l*D_ + c4]);
        const float p = pm[l];
        *(float4*)&dst[l*LDX + c4] =
            make_float4((e.x+pe.x)*p, (e.y+pe.y)*p, (e.z+pe.z)*p, (e.w+pe.w)*p);
    }
}

__global__ void __launch_bounds__(TPB, 4)
fissa_kernel(const int* __restrict__ ui, const int* __restrict__ pi,
             const int* __restrict__ ni, const float* __restrict__ pmask,
             const float* __restrict__ item_emb, const float* __restrict__ pos_emb,
             const float* __restrict__ Qs, const float* __restrict__ Ks,
             const float* __restrict__ Vs,
             const float* __restrict__ c1w, const float* __restrict__ c1b,
             const float* __restrict__ c2w, const float* __restrict__ c2b,
             const float* __restrict__ qitem,
             const float* __restrict__ Klba, const float* __restrict__ Vlba,
             const float* __restrict__ l1w, const float* __restrict__ l1b,
             const float* __restrict__ l2w, const float* __restrict__ l2b,
             const float* __restrict__ gw, const float* __restrict__ gb,
             float* __restrict__ out) {
    extern __shared__ float sm[];
    float* s_x   = sm + OFF_X;
    float* t1    = sm + OFF_T1;
    float* t2    = sm + OFF_T2;
    float* s_sc  = sm + OFF_SC;
    float* s_pm  = sm + OFF_PM;
    float* s_g1  = sm + OFF_G1;
    float* s_glo = sm + OFF_GLO;
    float* s_gw  = sm + OFF_GW;

    const int b    = blockIdx.x;
    const int tid  = threadIdx.x;
    const int lane = tid & 31;
    const int wid  = tid >> 5;

    // ---- prologue ----
    if (tid < 192) s_gw[tid] = gw[tid];
    if (tid < L_)  s_pm[tid] = pmask[b*L_ + tid];
    __syncthreads();

    build_inputs(s_x, ui + b*L_, item_emb, pos_emb, s_pm);
    // g1[l] = ie[l] . gw[0:64]
    for (int l = wid; l < L_; l += 8) {
        const int it = __ldg(&ui[b*L_ + l]);
        float v = item_emb[it*D_ + lane] * s_gw[lane]
                + item_emb[it*D_ + lane + 32] * s_gw[lane + 32];
        v = warp_sum(v);
        if (lane == 0) s_g1[l] = v;
    }
    __syncthreads();
    ln_rows(s_x);                        // x = inputs = LN((ie + pos) * pm)
    __syncthreads();

    // ---- S self-attention blocks ----
    for (int s = 0; s < S_; ++s) {
        mm_LW(t1, s_x, Qs + s*D_*D_);            // Qx
        mm_LW(t2, s_x, Ks + s*D_*D_);            // Kx
        __syncthreads();
        mm_scores(s_sc, t1, t2, s_pm);
        __syncthreads();
        mm_LW(t1, s_x, Vs + s*D_*D_);            // Vx (Qx dead)
        __syncthreads();
        mm_SM<false>(t2, s_sc, t1, s_x, nullptr, nullptr);   // att = sc@Vx + x
        __syncthreads();
        // stage c1 (scores dead) + LN(att)
        for (int idx = tid; idx < L_*L_; idx += TPB) {
            const int i = idx / L_, j = idx - i*L_;
            s_sc[i*LDM + j] = __ldg(&c1w[s*L_*L_ + idx]);
        }
        ln_rows(t2);
        __syncthreads();
        mm_SM<true>(t1, s_sc, t2, nullptr, c1b + s*L_, nullptr);  // h
        __syncthreads();
        for (int idx = tid; idx < L_*L_; idx += TPB) {
            const int i = idx / L_, j = idx - i*L_;
            s_sc[i*LDM + j] = __ldg(&c2w[s*L_*L_ + idx]);
        }
        __syncthreads();
        mm_SM<false>(s_x, s_sc, t1, t2, c2b + s*L_, s_pm);   // ff -> x
        __syncthreads();
        ln_rows(s_x);
        __syncthreads();
    }
    // s_x = loc from here on (untouched below)

    // ---- LBA global attention (tile-free formulation) ----
    // regenerate `inputs` into t1 (identical deterministic recompute)
    build_inputs(t1, ui + b*L_, item_emb, pos_emb, s_pm);
    __syncthreads();
    ln_rows(t1);
    __syncthreads();

    float* kq = s_sc;          // 64
    float* lg = s_sc + 64;     // 50 logits -> softmax probs
    float* wv = s_sc + 128;    // 64 column sums

    // kq[e] = Klba[e,:] . q
    for (int e = wid; e < D_; e += 8) {
        float v = __ldg(&Klba[e*D_ + lane]) * __ldg(&qitem[lane])
                + __ldg(&Klba[e*D_ + lane + 32]) * __ldg(&qitem[lane + 32]);
        v = warp_sum(v);
        if (lane == 0) kq[e] = v;
    }
    __syncthreads();
    // lg[l] = inputs[l] . kq  (+ key mask)
    for (int l = wid; l < L_; l += 8) {
        float v = t1[l*LDX + lane] * kq[lane]
                + t1[l*LDX + lane + 32] * kq[lane + 32];
        v = warp_sum(v);
        if (lane == 0) lg[l] = (s_pm[l] == 0.0f) ? NEGV : v;
    }
    __syncthreads();
    // softmax over 50 (warp 0)
    if (wid == 0) {
        float v0 = (lane < L_) ? lg[lane] : -3.0e38f;
        float v1 = (lane + 32 < L_) ? lg[lane + 32] : -3.0e38f;
        float m = warp_max(fmaxf(v0, v1));
        float e0 = (lane < L_) ? expf(v0 - m) : 0.0f;
        float e1 = (lane + 32 < L_) ? expf(v1 - m) : 0.0f;
        float ssum = warp_sum(e0 + e1);
        if (lane < L_)      lg[lane]      = e0 / ssum;
        if (lane + 32 < L_) lg[lane + 32] = e1 / ssum;
    }
    __syncthreads();
    // wv[e] = sum_l p[l] * inputs[l, e]
    if (tid < D_) {
        float a = 0.0f;
        for (int l = 0; l < L_; ++l) a = fmaf(lg[l], t1[l*LDX + tid], a);
        wv[tid] = a;
    }
    __syncthreads();
    // glo[d] = sum_e wv[e] * Vlba[e, d]
    if (tid < D_) {
        float a = 0.0f;
        for (int e = 0; e < D_; ++e) a = fmaf(wv[e], __ldg(&Vlba[e*D_ + tid]), a);
        s_glo[tid] = a;
    }
    __syncthreads();
    // LN -> l1/l2 residual -> LN -> gglo scalar (warp 0)
    if (wid == 0) {
        float v0 = s_glo[lane], v1 = s_glo[lane + 32];
        float mean = warp_sum(v0 + v1) * (1.0f/64.0f);
        float d0 = v0 - mean, d1 = v1 - mean;
        float var = warp_sum(d0*d0 + d1*d1) * (1.0f/64.0f);
        float inv = rsqrtf(var + 1e-8f);
        float g0 = d0 * inv, g1v = d1 * inv;
        const float w1 = l1w[0], bb1 = l1b[0], w2 = l2w[0], bb2 = l2b[0];
        float h0 = fmaxf(w1*g0 + bb1, 0.0f);
        float h1 = fmaxf(w1*g1v + bb1, 0.0f);
        g0  = w2*h0 + bb2 + g0;
        g1v = w2*h1 + bb2 + g1v;
        mean = warp_sum(g0 + g1v) * (1.0f/64.0f);
        d0 = g0 - mean; d1 = g1v - mean;
        var = warp_sum(d0*d0 + d1*d1) * (1.0f/64.0f);
        inv = rsqrtf(var + 1e-8f);
        g0 = d0 * inv; g1v = d1 * inv;
        s_glo[lane] = g0; s_glo[lane + 32] = g1v;
        float gg = warp_sum(g0 * s_gw[64 + lane] + g1v * s_gw[96 + lane]);
        if (lane == 0) s_gw[192] = gg;   // glo . gw[64:128]
    }
    __syncthreads();

    // ---- gated fusion + final LN + pos/neg dots ----
    const float gbias = gb[0];
    for (int t = wid; t < 2*L_; t += 8) {
        const int pn = (t >= L_);
        const int l  = t - pn*L_;
        const int*  items = pn ? ni : pi;
        const int   it = __ldg(&items[b*L_ + l]);
        const float e0 = item_emb[it*D_ + lane];
        const float e1 = item_emb[it*D_ + lane + 32];
        const float dot3 = warp_sum(e0 * s_gw[128 + lane] + e1 * s_gw[160 + lane]);
        const float logit = s_g1[l] + s_gw[192] + dot3 + gbias;
        const float g = sigmoidf_(sigmoidf_(logit));
        float o0 = (s_x[l*LDX + lane]      * g + s_glo[lane]      * (1.0f - g)) * s_pm[l];
        float o1 = (s_x[l*LDX + lane + 32] * g + s_glo[lane + 32] * (1.0f - g)) * s_pm[l];
        const float mean = warp_sum(o0 + o1) * (1.0f/64.0f);
        const float d0 = o0 - mean, d1 = o1 - mean;
        const float var = warp_sum(d0*d0 + d1*d1) * (1.0f/64.0f);
        const float inv = rsqrtf(var + 1e-8f);
        const float r = warp_sum(d0*inv*e0 + d1*inv*e1);
        if (lane == 0) out[pn*B_*L_ + b*L_ + l] = r;
    }
}

extern "C" void kernel_launch(void* const* d_in, const int* in_sizes, int n_in,
                              void* d_out, int out_size) {
    const int*   ui       = (const int*)  d_in[0];
    const int*   pi       = (const int*)  d_in[1];
    const int*   ni       = (const int*)  d_in[2];
    const float* pmask    = (const float*)d_in[3];
    const float* item_emb = (const float*)d_in[4];
    const float* pos_emb  = (const float*)d_in[5];
    const float* Qs       = (const float*)d_in[6];
    const float* Ks       = (const float*)d_in[7];
    const float* Vs       = (const float*)d_in[8];
    const float* c1w      = (const float*)d_in[9];
    const float* c1b      = (const float*)d_in[10];
    const float* c2w      = (const float*)d_in[11];
    const float* c2b      = (const float*)d_in[12];
    const float* qitem    = (const float*)d_in[13];
    const float* Klba     = (const float*)d_in[14];
    const float* Vlba     = (const float*)d_in[15];
    const float* l1w      = (const float*)d_in[16];
    const float* l1b      = (const float*)d_in[17];
    const float* l2w      = (const float*)d_in[18];
    const float* l2b      = (const float*)d_in[19];
    const float* gw       = (const float*)d_in[20];
    const float* gb       = (const float*)d_in[21];
    float* out = (float*)d_out;

    cudaFuncSetAttribute(fissa_kernel,
                         cudaFuncAttributeMaxDynamicSharedMemorySize, SMEM_BYTES);
    fissa_kernel<<<B_, TPB, SMEM_BYTES>>>(ui, pi, ni, pmask, item_emb, pos_emb,
                                          Qs, Ks, Vs, c1w, c1b, c2w, c2b, qitem,
                                          Klba, Vlba, l1w, l1b, l2w, l2b, gw, gb,
                                          out);
}